// round 3
// baseline (speedup 1.0000x reference)
#include <cuda_runtime.h>
#include <cstdint>
#include <math.h>

// Problem shapes (fixed for this bench)
#define BATCH 2
#define DK 128
#define DV 512
#define NQ 4096         // H*W
#define NM 8192         // T*H*W
#define NTHREADS 256
#define PSCALAR 40.0f
#define DELTA 27.6310211159f     // -ln(1e-12)

// GEMM tiling
#define QTILE 128
#define MC 128
#define NSEG 4
#define CAP 1024

typedef unsigned long long ull;

// -------- device scratch (static: no allocations allowed) --------
__device__ float g_qk[BATCH * DK * NQ];          // compacted qkey
__device__ float g_mk[BATCH * DK * NM];          // compacted mkey
__device__ float g_mvT[(size_t)BATCH * NM * DV]; // compacted, transposed mval [b][m][v]
__device__ int   g_qlist[BATCH * NQ];
__device__ int   g_mlist[BATCH * NM];
__device__ int   g_nq[BATCH];
__device__ int   g_nm[BATCH];
__device__ int2  g_cand[(size_t)BATCH * NQ * CAP];  // (m_compact, logit bits)
__device__ int   g_ccnt[BATCH * NQ];

// monotone float<->uint encoding for atomicMax on floats (incl. negatives)
__device__ __forceinline__ unsigned fenc(float f) {
    unsigned u = __float_as_uint(f);
    return (u & 0x80000000u) ? ~u : (u | 0x80000000u);
}
__device__ __forceinline__ float fdec(unsigned e) {
    unsigned u = (e & 0x80000000u) ? (e & 0x7FFFFFFFu) : ~e;
    return __uint_as_float(u);
}

// -------- kernel 0: zero output + candidate counters --------
__global__ void zero_kernel(float4* out, int n4) {
    int i = blockIdx.x * blockDim.x + threadIdx.x;
    if (i < n4) out[i] = make_float4(0.f, 0.f, 0.f, 0.f);
    if (i < BATCH * NQ / 4) ((int4*)g_ccnt)[i] = make_int4(0, 0, 0, 0);
}

// -------- kernel 1: deterministic stream compaction of masks --------
__global__ void compact_kernel(const unsigned int* qmask, const unsigned int* mmask) {
    int b = blockIdx.x;
    int which = blockIdx.y;    // 0 = q, 1 = m
    const unsigned int* mask = which ? (mmask + b * NM) : (qmask + b * NQ);
    int n = which ? NM : NQ;
    int* list = which ? (g_mlist + b * NM) : (g_qlist + b * NQ);

    __shared__ int wcnt[NTHREADS / 32];
    __shared__ int sbase;
    int tid = threadIdx.x, lane = tid & 31, wid = tid >> 5;
    if (tid == 0) sbase = 0;
    __syncthreads();

    for (int start = 0; start < n; start += NTHREADS) {
        int idx = start + tid;
        int flag = (idx < n) && (mask[idx] != 0u);
        unsigned bal = __ballot_sync(0xFFFFFFFFu, flag);
        int pre = __popc(bal & ((1u << lane) - 1u));
        if (lane == 0) wcnt[wid] = __popc(bal);
        __syncthreads();
        int wbase = 0, tot = 0;
#pragma unroll
        for (int w = 0; w < NTHREADS / 32; w++) {
            if (w < wid) wbase += wcnt[w];
            tot += wcnt[w];
        }
        int base = sbase;
        if (flag) list[base + wbase + pre] = idx;
        __syncthreads();
        if (tid == 0) sbase = base + tot;
        __syncthreads();
    }
    if (tid == 0) {
        if (which) g_nm[b] = sbase; else g_nq[b] = sbase;
    }
}

// -------- kernel 2: gather-pack qkey/mkey; zero-fill padded tails --------
__global__ void pack_kernel(const float* qkey, const float* mkey) {
    int d = blockIdx.x;
    int b = blockIdx.y;
    int nq = g_nq[b], nm = g_nm[b];
    const float* qs = qkey + (size_t)(b * DK + d) * NQ;
    const float* ms = mkey + (size_t)(b * DK + d) * NM;
    float* qd = g_qk + (size_t)(b * DK + d) * NQ;
    float* md = g_mk + (size_t)(b * DK + d) * NM;
    for (int i = threadIdx.x; i < nq; i += blockDim.x) qd[i] = qs[g_qlist[b * NQ + i]];
    for (int i = nq + threadIdx.x; i < NQ; i += blockDim.x) qd[i] = 0.f;
    for (int i = threadIdx.x; i < nm; i += blockDim.x) md[i] = ms[g_mlist[b * NM + i]];
    for (int i = nm + threadIdx.x; i < NM; i += blockDim.x) md[i] = 0.f;
}

// -------- kernel 2b: gather-transpose mval -> g_mvT[b][m][v] (compacted m) --------
__global__ void transpose_kernel(const float* __restrict__ mval) {
    __shared__ float t[32][33];
    int b = blockIdx.z;
    int nm = g_nm[b];
    int m0 = blockIdx.x * 32;
    if (m0 >= nm) return;
    int v0 = blockIdx.y * 32;
    int tx = threadIdx.x, ty = threadIdx.y;   // 32 x 8

    const float* mvb = mval + (size_t)b * DV * NM;
    int mg = (m0 + tx < nm) ? g_mlist[b * NM + m0 + tx] : -1;
#pragma unroll
    for (int vi = ty; vi < 32; vi += 8)
        t[tx][vi] = (mg >= 0) ? mvb[(size_t)(v0 + vi) * NM + mg] : 0.f;
    __syncthreads();

    float* dst = g_mvT + (size_t)b * NM * DV;
#pragma unroll
    for (int mi = ty; mi < 32; mi += 8)
        if (m0 + mi < nm)
            dst[(size_t)(m0 + mi) * DV + v0 + tx] = t[mi][tx];
}

// -------- kernel 3: QK GEMM (packed f32x2) + inline running-max candidate emission --------
__global__ __launch_bounds__(NTHREADS, 1)
void qk_kernel() {
    int b = blockIdx.z, seg = blockIdx.y;
    int nq = g_nq[b], nm = g_nm[b];
    int qi0 = blockIdx.x * QTILE;
    if (qi0 >= nq || nm == 0) return;
    int segsz = (((nm + NSEG - 1) / NSEG) + MC - 1) / MC * MC;
    int ms = seg * segsz;
    if (ms >= nm) return;
    int me = min(ms + segsz, nm);

    extern __shared__ float sm[];
    float* sQ = sm;                          // [DK][QTILE] 64KB
    float* sM = sQ + DK * QTILE;             // 2 x [DK][MC] 128KB
    unsigned* sGMax = (unsigned*)(sM + 2 * DK * MC);  // [QTILE]

    int tid = threadIdx.x;
    int tx = tid & 15;       // m: 8 each
    int ty = tid >> 4;       // q: 8 each

    if (tid < QTILE) sGMax[tid] = fenc(-3.0e38f);

    const float* qkb = g_qk + (size_t)b * DK * NQ;
    const float* mkb = g_mk + (size_t)b * DK * NM;

    for (int e = tid; e < DK * QTILE; e += NTHREADS) {
        int d = e >> 7, q = e & 127;
        sQ[e] = qkb[(size_t)d * NQ + qi0 + q];
    }

    int nch = (me - ms + MC - 1) / MC;

    auto issue = [&](int m0, int buf) {
        float* dst = sM + buf * DK * MC;
#pragma unroll
        for (int k = 0; k < 16; k++) {
            int idx = tid + k * NTHREADS;     // 4096 float4s
            int d = idx >> 5, j = idx & 31;
            const float* src = &mkb[(size_t)d * NM + m0 + j * 4];
            unsigned saddr = (unsigned)__cvta_generic_to_shared(&dst[d * MC + j * 4]);
            asm volatile("cp.async.cg.shared.global [%0], [%1], 16;" :: "r"(saddr), "l"(src));
        }
        asm volatile("cp.async.commit_group;");
    };

    issue(ms, 0);

    float cth[8];
#pragma unroll
    for (int j = 0; j < 8; j++) cth[j] = -3.0e38f;

    for (int c = 0; c < nch; c++) {
        int m0 = ms + c * MC;
        asm volatile("cp.async.wait_group 0;");
        __syncthreads();
        if (c + 1 < nch) issue(ms + (c + 1) * MC, (c + 1) & 1);

        const float* sMb = sM + (c & 1) * DK * MC;

#pragma unroll
        for (int j = 0; j < 8; j++) cth[j] = fdec(sGMax[ty * 8 + j]);

        // packed accumulators: acc2[j][i] holds (q_j*m_{2i}, q_j*m_{2i+1})
        ull acc2[8][4];
#pragma unroll
        for (int j = 0; j < 8; j++)
#pragma unroll
            for (int i = 0; i < 4; i++) acc2[j][i] = 0ull;

#pragma unroll 4
        for (int d = 0; d < DK; d++) {
            ulonglong2 ma = *(const ulonglong2*)&sMb[d * MC + tx * 8];
            ulonglong2 mb2 = *(const ulonglong2*)&sMb[d * MC + tx * 8 + 4];
            ull m2[4] = {ma.x, ma.y, mb2.x, mb2.y};
            float4 q0v = *(const float4*)&sQ[d * QTILE + ty * 8];
            float4 q1v = *(const float4*)&sQ[d * QTILE + ty * 8 + 4];
            float qq[8] = {q0v.x, q0v.y, q0v.z, q0v.w, q1v.x, q1v.y, q1v.z, q1v.w};
            ull q2[8];
#pragma unroll
            for (int j = 0; j < 8; j++) {
                unsigned qi = __float_as_uint(qq[j]);
                asm("mov.b64 %0, {%1, %1};" : "=l"(q2[j]) : "r"(qi));
            }
#pragma unroll
            for (int j = 0; j < 8; j++)
#pragma unroll
                for (int i = 0; i < 4; i++)
                    asm("fma.rn.f32x2 %0, %1, %2, %0;"
                        : "+l"(acc2[j][i]) : "l"(q2[j]), "l"(m2[i]));
        }

        // epilogue: unpack, scale, per-q block max, rare candidate insertion
#pragma unroll
        for (int j = 0; j < 8; j++) {
            float sv[8];
#pragma unroll
            for (int i = 0; i < 4; i++) {
                ull a = acc2[j][i];
                sv[2 * i]     = __uint_as_float((unsigned)a) * PSCALAR;
                sv[2 * i + 1] = __uint_as_float((unsigned)(a >> 32)) * PSCALAR;
            }
            float bm = -3.0e38f;
#pragma unroll
            for (int i = 0; i < 8; i++) bm = fmaxf(bm, sv[i]);

            if (bm > cth[j] - DELTA) {
                int q = qi0 + ty * 8 + j;
                if (q < nq) {
                    unsigned olde = atomicMax(&sGMax[ty * 8 + j], fenc(bm));
                    float th = fmaxf(fdec(olde), bm);
                    cth[j] = th;
#pragma unroll
                    for (int i = 0; i < 8; i++) {
                        int mg = m0 + tx * 8 + i;
                        if (mg < me && sv[i] > th - DELTA) {
                            int pos = atomicAdd(&g_ccnt[b * NQ + q], 1);
                            if (pos < CAP)
                                g_cand[((size_t)b * NQ + q) * CAP + pos] =
                                    make_int2(mg, __float_as_int(sv[i]));
                        }
                    }
                } else {
                    cth[j] = fmaxf(cth[j], bm);  // phantom q: local suppress
                }
            }
        }
    }
}

// -------- kernel 4: finalize — exact max/sum + deterministic sparse gather --------
__global__ __launch_bounds__(NTHREADS)
void finalize_kernel(float* __restrict__ out) {
    int b = blockIdx.y;
    int nq = g_nq[b], nm = g_nm[b];
    int wid = threadIdx.x >> 5, lane = threadIdx.x & 31;
    int q = blockIdx.x * 8 + wid;
    if (q >= nq || nm == 0) return;

    size_t cbase = ((size_t)b * NQ + q) * CAP;
    int c = min(g_ccnt[b * NQ + q], CAP);

    // pass 1: exact max (order-free)
    float mx = -3.0e38f;
    for (int i = lane; i < c; i += 32)
        mx = fmaxf(mx, __int_as_float(g_cand[cbase + i].y));
#pragma unroll
    for (int off = 16; off; off >>= 1)
        mx = fmaxf(mx, __shfl_xor_sync(0xFFFFFFFFu, mx, off));

    // pass 2: deterministic fixed-point exp sum
    unsigned long long iacc = 0;
    for (int i = lane; i < c; i += 32) {
        float s = __int_as_float(g_cand[cbase + i].y);
        if (s > mx - DELTA) {
            float w = expf(s - mx);
            iacc += (unsigned long long)((double)w * 4503599627370496.0);  // 2^52
        }
    }
#pragma unroll
    for (int off = 16; off; off >>= 1)
        iacc += __shfl_xor_sync(0xFFFFFFFFu, iacc, off);
    double dsum = (double)iacc * (1.0 / 4503599627370496.0);
    float inv = (float)(1.0 / dsum);

    // pass 3: extract passing events in ascending-m order, gather mvT rows
    float ov[16];
#pragma unroll
    for (int j = 0; j < 16; j++) ov[j] = 0.f;

    const float* mvtb = g_mvT + (size_t)b * NM * DV;
    int last = -1;
    while (true) {
        int mym = 0x7FFFFFFF; float myw = 0.f;
        for (int i = lane; i < c; i += 32) {
            int2 e = g_cand[cbase + i];
            float s = __int_as_float(e.y);
            if (s > mx - DELTA && e.x > last && e.x < mym) {
                mym = e.x;
                myw = expf(s - mx);
            }
        }
#pragma unroll
        for (int off = 16; off; off >>= 1) {
            int om = __shfl_xor_sync(0xFFFFFFFFu, mym, off);
            float ow = __shfl_xor_sync(0xFFFFFFFFu, myw, off);
            if (om < mym) { mym = om; myw = ow; }
        }
        if (mym == 0x7FFFFFFF) break;
        const float* row = mvtb + (size_t)mym * DV;
#pragma unroll
        for (int j = 0; j < 16; j++)
            ov[j] += myw * row[lane + 32 * j];
        last = mym;
    }

    int qg = g_qlist[b * NQ + q];
    float* ob = out + (size_t)b * DV * NQ + qg;
#pragma unroll
    for (int j = 0; j < 16; j++)
        ob[(size_t)(lane + 32 * j) * NQ] = ov[j] * inv;
}

// -------- launch --------
extern "C" void kernel_launch(void* const* d_in, const int* in_sizes, int n_in,
                              void* d_out, int out_size) {
    const float*        qkey  = (const float*)d_in[0];
    // d_in[1] = qval (unused by the reference math)
    const unsigned int* qmask = (const unsigned int*)d_in[2];
    const float*        mkey  = (const float*)d_in[3];
    const float*        mval  = (const float*)d_in[4];
    const unsigned int* mmask = (const unsigned int*)d_in[5];
    float* out = (float*)d_out;

    int n4 = BATCH * DV * NQ / 4;
    zero_kernel<<<(n4 + 255) / 256, 256>>>((float4*)out, n4);

    compact_kernel<<<dim3(BATCH, 2), NTHREADS>>>(qmask, mmask);

    pack_kernel<<<dim3(DK, BATCH), NTHREADS>>>(qkey, mkey);

    transpose_kernel<<<dim3(NM / 32, DV / 32, BATCH), dim3(32, 8)>>>(mval);

    size_t smemBytes = (size_t)(DK * QTILE + 2 * DK * MC) * sizeof(float) + QTILE * sizeof(unsigned);
    cudaFuncSetAttribute(qk_kernel, cudaFuncAttributeMaxDynamicSharedMemorySize, (int)smemBytes);
    qk_kernel<<<dim3(NQ / QTILE, NSEG, BATCH), NTHREADS, smemBytes>>>();

    finalize_kernel<<<dim3(NQ / 8, BATCH), NTHREADS>>>(out);
}

// round 5
// speedup vs baseline: 1.3174x; 1.3174x over previous
#include <cuda_runtime.h>
#include <cstdint>
#include <math.h>

// Problem shapes (fixed for this bench)
#define BATCH 2
#define DK 128
#define DV 512
#define NQ 4096         // H*W
#define NM 8192         // T*H*W
#define NTHREADS 256
#define PSCALAR 40.0f
// -ln(1e-12) + 6.0 slack for single-pass tf32 screening error (13 sigma)
#define DELTAS 33.6310211159f

#define QTILE 128
#define MC 128
#define NSEG 4
#define CAP 1024
#define RS 136           // padded smem row stride in floats (conflict-free frags)

// smem byte offsets
#define SM_GMAX  0
#define SM_A     512
#define SM_B     (512 + 128 * RS * 4)            // 70144
#define SM_TOTAL (SM_B + 2 * 128 * RS * 4)       // 209408

typedef unsigned long long ull;

// -------- device scratch (static: no allocations allowed) --------
__device__ float g_qk [BATCH * DK * NQ];          // compacted qkey (exact f32) [b][d][q]
__device__ float g_qkt[BATCH * DK * NQ];          // tf32-rounded copy
__device__ float g_mk [BATCH * DK * NM];          // compacted mkey (exact f32) [b][d][m]
__device__ float g_mkt[BATCH * DK * NM];          // tf32-rounded copy
__device__ float g_mkT[(size_t)BATCH * NM * DK];  // exact mkey transposed [b][m][d]
__device__ int   g_qlist[BATCH * NQ];
__device__ int   g_mlist[BATCH * NM];
__device__ int   g_nq[BATCH];
__device__ int   g_nm[BATCH];
__device__ int2  g_cand[(size_t)BATCH * NQ * CAP];  // (m_compact, logit bits)
__device__ int   g_ccnt[BATCH * NQ];

// monotone float<->uint encoding for atomicMax on floats (incl. negatives)
__device__ __forceinline__ unsigned fenc(float f) {
    unsigned u = __float_as_uint(f);
    return (u & 0x80000000u) ? ~u : (u | 0x80000000u);
}
__device__ __forceinline__ float fdec(unsigned e) {
    unsigned u = (e & 0x80000000u) ? (e & 0x7FFFFFFFu) : ~e;
    return __uint_as_float(u);
}
__device__ __forceinline__ float to_tf32(float x) {
    uint32_t r;
    asm("cvt.rna.tf32.f32 %0, %1;" : "=r"(r) : "f"(x));
    return __uint_as_float(r);
}

#define MMA_TF32(c0, c1, c2, c3, a0, a1, a2, a3, b0, b1) \
    asm volatile("mma.sync.aligned.m16n8k8.row.col.f32.tf32.tf32.f32 " \
        "{%0,%1,%2,%3}, {%4,%5,%6,%7}, {%8,%9}, {%0,%1,%2,%3};" \
        : "+f"(c0), "+f"(c1), "+f"(c2), "+f"(c3) \
        : "r"(a0), "r"(a1), "r"(a2), "r"(a3), "r"(b0), "r"(b1))

// -------- kernel 0: zero output + candidate counters --------
__global__ void zero_kernel(float4* out, int n4) {
    int i = blockIdx.x * blockDim.x + threadIdx.x;
    if (i < n4) out[i] = make_float4(0.f, 0.f, 0.f, 0.f);
    if (i < BATCH * NQ / 4) ((int4*)g_ccnt)[i] = make_int4(0, 0, 0, 0);
}

// -------- kernel 1: deterministic stream compaction of masks --------
__global__ void compact_kernel(const unsigned int* qmask, const unsigned int* mmask) {
    int b = blockIdx.x;
    int which = blockIdx.y;    // 0 = q, 1 = m
    const unsigned int* mask = which ? (mmask + b * NM) : (qmask + b * NQ);
    int n = which ? NM : NQ;
    int* list = which ? (g_mlist + b * NM) : (g_qlist + b * NQ);

    __shared__ int wcnt[NTHREADS / 32];
    __shared__ int sbase;
    int tid = threadIdx.x, lane = tid & 31, wid = tid >> 5;
    if (tid == 0) sbase = 0;
    __syncthreads();

    for (int start = 0; start < n; start += NTHREADS) {
        int idx = start + tid;
        int flag = (idx < n) && (mask[idx] != 0u);
        unsigned bal = __ballot_sync(0xFFFFFFFFu, flag);
        int pre = __popc(bal & ((1u << lane) - 1u));
        if (lane == 0) wcnt[wid] = __popc(bal);
        __syncthreads();
        int wbase = 0, tot = 0;
#pragma unroll
        for (int w = 0; w < NTHREADS / 32; w++) {
            if (w < wid) wbase += wcnt[w];
            tot += wcnt[w];
        }
        int base = sbase;
        if (flag) list[base + wbase + pre] = idx;
        __syncthreads();
        if (tid == 0) sbase = base + tot;
        __syncthreads();
    }
    if (tid == 0) {
        if (which) g_nm[b] = sbase; else g_nq[b] = sbase;
    }
}

// -------- kernel 2: gather-pack qkey/mkey (+tf32 copies); zero-pad tails --------
__global__ void pack_kernel(const float* qkey, const float* mkey) {
    int d = blockIdx.x;
    int b = blockIdx.y;
    int nq = g_nq[b], nm = g_nm[b];
    const float* qs = qkey + (size_t)(b * DK + d) * NQ;
    const float* ms = mkey + (size_t)(b * DK + d) * NM;
    size_t qoff = (size_t)(b * DK + d) * NQ;
    size_t moff = (size_t)(b * DK + d) * NM;
    for (int i = threadIdx.x; i < NQ; i += blockDim.x) {
        float v = (i < nq) ? qs[g_qlist[b * NQ + i]] : 0.f;
        g_qk[qoff + i] = v;
        g_qkt[qoff + i] = to_tf32(v);
    }
    for (int i = threadIdx.x; i < NM; i += blockDim.x) {
        float v = (i < nm) ? ms[g_mlist[b * NM + i]] : 0.f;
        g_mk[moff + i] = v;
        g_mkt[moff + i] = to_tf32(v);
    }
}

// -------- kernel 2b: transpose g_mk -> g_mkT [b][m][d] --------
__global__ void transposeK_kernel() {
    __shared__ float t[32][33];
    int b = blockIdx.z;
    int m0 = blockIdx.x * 32, d0 = blockIdx.y * 32;
    int tx = threadIdx.x, ty = threadIdx.y;   // 32 x 8
    const float* src = g_mk + (size_t)b * DK * NM;
#pragma unroll
    for (int i = ty; i < 32; i += 8)
        t[i][tx] = src[(size_t)(d0 + i) * NM + m0 + tx];
    __syncthreads();
    float* dst = g_mkT + (size_t)b * NM * DK;
#pragma unroll
    for (int i = ty; i < 32; i += 8)
        dst[(size_t)(m0 + i) * DK + d0 + tx] = t[tx][i];
}

// -------- kernel 3: tf32 mma.sync screening GEMM + candidate emission --------
__global__ __launch_bounds__(NTHREADS, 1)
void qk_mma_kernel() {
    int b = blockIdx.z, seg = blockIdx.y;
    int nq = g_nq[b], nm = g_nm[b];
    int qi0 = blockIdx.x * QTILE;
    if (qi0 >= nq || nm == 0) return;
    int segsz = (((nm + NSEG - 1) / NSEG) + MC - 1) / MC * MC;
    int ms = seg * segsz;
    if (ms >= nm) return;
    int me = min(ms + segsz, nm);
    int nch = (me - ms + MC - 1) / MC;

    extern __shared__ char smem[];
    unsigned* sGMax = (unsigned*)(smem + SM_GMAX);
    float* sA = (float*)(smem + SM_A);

    int tid = threadIdx.x, lane = tid & 31, wid = tid >> 5;
    int gr = lane >> 2, tig = lane & 3;
    int warp_q0 = (wid >> 2) * 64;
    int warp_m0 = (wid & 3) * 32;

    if (tid < QTILE) sGMax[tid] = fenc(-3.0e38f);

    // stage A tile [k=128][q=128] from g_qkt (tf32 values)
    const float* qkt = g_qkt + (size_t)b * DK * NQ;
#pragma unroll
    for (int it = 0; it < 16; it++) {
        int idx = tid + it * NTHREADS;   // 4096 float4 slots
        int k = idx >> 5, j = idx & 31;
        const float* src = &qkt[(size_t)k * NQ + qi0 + j * 4];
        unsigned sa = (unsigned)__cvta_generic_to_shared(sA + k * RS + j * 4);
        asm volatile("cp.async.cg.shared.global [%0], [%1], 16;" :: "r"(sa), "l"(src));
    }
    asm volatile("cp.async.commit_group;");

    const float* mkt = g_mkt + (size_t)b * DK * NM;
    auto issueB = [&](int m0, int buf) {
        float* dst = (float*)(smem + SM_B) + buf * 128 * RS;
#pragma unroll
        for (int it = 0; it < 16; it++) {
            int idx = tid + it * NTHREADS;
            int k = idx >> 5, j = idx & 31;
            const float* src = &mkt[(size_t)k * NM + m0 + j * 4];
            unsigned sa = (unsigned)__cvta_generic_to_shared(dst + k * RS + j * 4);
            asm volatile("cp.async.cg.shared.global [%0], [%1], 16;" :: "r"(sa), "l"(src));
        }
        asm volatile("cp.async.commit_group;");
    };

    issueB(ms, 0);

    for (int c = 0; c < nch; c++) {
        int mt0 = ms + c * MC;
        asm volatile("cp.async.wait_group 0;");
        __syncthreads();
        if (c + 1 < nch) issueB(ms + (c + 1) * MC, (c + 1) & 1);

        const float* sB = (const float*)(smem + SM_B) + (c & 1) * 128 * RS;

        float acc[4][4][4];
#pragma unroll
        for (int qf = 0; qf < 4; qf++)
#pragma unroll
            for (int nf = 0; nf < 4; nf++)
#pragma unroll
                for (int r = 0; r < 4; r++) acc[qf][nf][r] = 0.f;

#pragma unroll 4
        for (int s = 0; s < 16; s++) {
            const float* rA0 = sA + (s * 8 + tig) * RS;
            const float* rA4 = rA0 + 4 * RS;
            const float* rB0 = sB + (s * 8 + tig) * RS;
            const float* rB4 = rB0 + 4 * RS;
            uint32_t a[4][4], bb[4][2];
#pragma unroll
            for (int qf = 0; qf < 4; qf++) {
                int base = warp_q0 + qf * 16 + gr;
                a[qf][0] = __float_as_uint(rA0[base]);
                a[qf][1] = __float_as_uint(rA0[base + 8]);
                a[qf][2] = __float_as_uint(rA4[base]);
                a[qf][3] = __float_as_uint(rA4[base + 8]);
            }
#pragma unroll
            for (int nf = 0; nf < 4; nf++) {
                int bn = warp_m0 + nf * 8 + gr;
                bb[nf][0] = __float_as_uint(rB0[bn]);
                bb[nf][1] = __float_as_uint(rB4[bn]);
            }
#pragma unroll
            for (int qf = 0; qf < 4; qf++)
#pragma unroll
                for (int nf = 0; nf < 4; nf++)
                    MMA_TF32(acc[qf][nf][0], acc[qf][nf][1], acc[qf][nf][2], acc[qf][nf][3],
                             a[qf][0], a[qf][1], a[qf][2], a[qf][3],
                             bb[nf][0], bb[nf][1]);
        }

        // epilogue: per q-row block max + rare candidate emission
        int mbw = mt0 + warp_m0;
#pragma unroll
        for (int qf = 0; qf < 4; qf++) {
#pragma unroll
            for (int h = 0; h < 2; h++) {
                int qrow = warp_q0 + qf * 16 + gr + h * 8;
                int q = qi0 + qrow;
                float sv[8];
                float bm = -3.0e38f;
#pragma unroll
                for (int nf = 0; nf < 4; nf++)
#pragma unroll
                    for (int col = 0; col < 2; col++) {
                        int ii = nf * 2 + col;
                        sv[ii] = acc[qf][nf][h * 2 + col] * PSCALAR;
                        int mg = mbw + nf * 8 + 2 * tig + col;
                        if (mg < me) bm = fmaxf(bm, sv[ii]);
                    }
                if (q < nq && bm > fdec(sGMax[qrow]) - DELTAS) {
                    unsigned olde = atomicMax(&sGMax[qrow], fenc(bm));
                    float th = fmaxf(fdec(olde), bm);
#pragma unroll
                    for (int nf = 0; nf < 4; nf++)
#pragma unroll
                        for (int col = 0; col < 2; col++) {
                            int ii = nf * 2 + col;
                            int mg = mbw + nf * 8 + 2 * tig + col;
                            if (mg < me && sv[ii] > th - DELTAS) {
                                int pos = atomicAdd(&g_ccnt[b * NQ + q], 1);
                                if (pos < CAP)
                                    g_cand[((size_t)b * NQ + q) * CAP + pos] =
                                        make_int2(mg, __float_as_int(sv[ii]));
                            }
                        }
                }
            }
        }
        __syncthreads();
    }
}

// -------- kernel 4: finalize — exact logits on deterministic set + softmax + gather --------
__global__ __launch_bounds__(NTHREADS)
void finalize_kernel(const float* __restrict__ mval, float* __restrict__ out) {
    __shared__ float sQc[8 * DK];
    int b = blockIdx.y;
    int nq = g_nq[b], nm = g_nm[b];
    int wid = threadIdx.x >> 5, lane = threadIdx.x & 31;
    int q = blockIdx.x * 8 + wid;
    if (nm == 0 || q >= nq) return;

    // load this warp's exact q column into smem
    for (int d = lane; d < DK; d += 32)
        sQc[wid * DK + d] = g_qk[(size_t)(b * DK + d) * NQ + q];
    __syncwarp();

    size_t cbase = ((size_t)b * NQ + q) * CAP;
    int c = min(g_ccnt[b * NQ + q], CAP);

    // screened max (order-free) -> deterministic candidate filter
    float mxs = -3.0e38f;
    for (int i = lane; i < c; i += 32)
        mxs = fmaxf(mxs, __int_as_float(g_cand[cbase + i].y));
#pragma unroll
    for (int off = 16; off; off >>= 1)
        mxs = fmaxf(mxs, __shfl_xor_sync(0xFFFFFFFFu, mxs, off));

    // pass A: exact fp32 logits for kept candidates; write back (non-kept -> -inf)
    const float* mkT = g_mkT + (size_t)b * NM * DK;
    const float4* qc4 = (const float4*)&sQc[wid * DK];
    float mx = -3.0e38f;
    for (int i = lane; i < c; i += 32) {
        int2 e = g_cand[cbase + i];
        float snew = -3.0e38f;
        if (__int_as_float(e.y) > mxs - DELTAS) {
            const float4* row = (const float4*)(mkT + (size_t)e.x * DK);
            float a0 = 0.f, a1 = 0.f, a2 = 0.f, a3 = 0.f;
#pragma unroll
            for (int j = 0; j < DK / 4; j++) {
                float4 mv = row[j];
                float4 qv = qc4[j];
                a0 = fmaf(qv.x, mv.x, a0);
                a1 = fmaf(qv.y, mv.y, a1);
                a2 = fmaf(qv.z, mv.z, a2);
                a3 = fmaf(qv.w, mv.w, a3);
            }
            snew = ((a0 + a1) + (a2 + a3)) * PSCALAR;
            mx = fmaxf(mx, snew);
        }
        g_cand[cbase + i].y = __float_as_int(snew);
    }
    __threadfence_block();
    __syncwarp();
#pragma unroll
    for (int off = 16; off; off >>= 1)
        mx = fmaxf(mx, __shfl_xor_sync(0xFFFFFFFFu, mx, off));

    // pass B: deterministic fixed-point exp sum over kept set (exact logits)
    unsigned long long iacc = 0;
    for (int i = lane; i < c; i += 32) {
        float s = __int_as_float(g_cand[cbase + i].y);
        if (s > -1.0e37f) {
            float w = expf(s - mx);
            iacc += (unsigned long long)((double)w * 4503599627370496.0);  // 2^52
        }
    }
#pragma unroll
    for (int off = 16; off; off >>= 1)
        iacc += __shfl_xor_sync(0xFFFFFFFFu, iacc, off);
    double dsum = (double)iacc * (1.0 / 4503599627370496.0);
    float inv = (float)(1.0 / dsum);

    // pass C: extract kept events in ascending-m order, gather mval columns
    float ov[16];
#pragma unroll
    for (int j = 0; j < 16; j++) ov[j] = 0.f;

    const float* mvb = mval + (size_t)b * DV * NM;
    int last = -1;
    while (true) {
        int mym = 0x7FFFFFFF; float myw = 0.f;
        for (int i = lane; i < c; i += 32) {
            int2 e = g_cand[cbase + i];
            float s = __int_as_float(e.y);
            if (s > -1.0e37f && e.x > last && e.x < mym) {
                mym = e.x;
                myw = expf(s - mx);
            }
        }
#pragma unroll
        for (int off = 16; off; off >>= 1) {
            int om = __shfl_xor_sync(0xFFFFFFFFu, mym, off);
            float ow = __shfl_xor_sync(0xFFFFFFFFu, myw, off);
            if (om < mym) { mym = om; myw = ow; }
        }
        if (mym == 0x7FFFFFFF) break;
        int mg = g_mlist[b * NM + mym];
        const float* col = mvb + mg;
#pragma unroll
        for (int j = 0; j < 16; j++)
            ov[j] += myw * col[(size_t)(lane + 32 * j) * NM];
        last = mym;
    }

    int qg = g_qlist[b * NQ + q];
    float* ob = out + (size_t)b * DV * NQ + qg;
#pragma unroll
    for (int j = 0; j < 16; j++)
        ob[(size_t)(lane + 32 * j) * NQ] = ov[j] * inv;
}

// -------- launch --------
extern "C" void kernel_launch(void* const* d_in, const int* in_sizes, int n_in,
                              void* d_out, int out_size) {
    const float*        qkey  = (const float*)d_in[0];
    // d_in[1] = qval (unused by the reference math)
    const unsigned int* qmask = (const unsigned int*)d_in[2];
    const float*        mkey  = (const float*)d_in[3];
    const float*        mval  = (const float*)d_in[4];
    const unsigned int* mmask = (const unsigned int*)d_in[5];
    float* out = (float*)d_out;

    int n4 = BATCH * DV * NQ / 4;
    zero_kernel<<<(n4 + 255) / 256, 256>>>((float4*)out, n4);

    compact_kernel<<<dim3(BATCH, 2), NTHREADS>>>(qmask, mmask);

    pack_kernel<<<dim3(DK, BATCH), NTHREADS>>>(qkey, mkey);

    transposeK_kernel<<<dim3(NM / 32, DK / 32, BATCH), dim3(32, 8)>>>();

    cudaFuncSetAttribute(qk_mma_kernel, cudaFuncAttributeMaxDynamicSharedMemorySize, SM_TOTAL);
    qk_mma_kernel<<<dim3(NQ / QTILE, NSEG, BATCH), NTHREADS, SM_TOTAL>>>();

    finalize_kernel<<<dim3(NQ / 8, BATCH), NTHREADS>>>(mval, out);
}

// round 6
// speedup vs baseline: 1.3804x; 1.0478x over previous
#include <cuda_runtime.h>
#include <cuda_bf16.h>
#include <cstdint>
#include <math.h>

// Problem shapes (fixed for this bench)
#define BATCH 2
#define DK 128
#define DV 512
#define NQ 4096         // H*W
#define NM 8192         // T*H*W
#define NTHREADS 256
#define PSCALAR 40.0f
// -ln(1e-12) + 8.0 slack for bf16 screening error (~11 sigma)
#define DELTAS 35.6310211159f

#define QTILE 128
#define MC 128
#define NSEG 4
#define CAP 1024
#define RS 136           // smem row stride in 32-bit words (conflict-free)

// smem byte offsets
#define SM_GMAX  0
#define SM_A     512                              // 64 rows x RS words
#define SM_B     (512 + 64 * RS * 4)              // 2 bufs x 64 x RS words
#define SM_TOTAL (SM_B + 2 * 64 * RS * 4)         // 104960 B

typedef unsigned long long ull;

// -------- device scratch (static: no allocations allowed) --------
__device__ uint32_t g_qkb[BATCH * (DK / 2) * NQ];   // packed bf16x2 (k-pair) [b][dp][q]
__device__ uint32_t g_mkb[BATCH * (DK / 2) * NM];   // packed bf16x2 (k-pair) [b][dp][m]
__device__ float    g_mkT[(size_t)BATCH * NM * DK]; // exact mkey transposed [b][m][d]
__device__ int      g_qlist[BATCH * NQ];
__device__ int      g_mlist[BATCH * NM];
__device__ int      g_nq[BATCH];
__device__ int      g_nm[BATCH];
__device__ int2     g_cand[(size_t)BATCH * NQ * CAP];  // (m_compact, logit bits)
__device__ int      g_ccnt[BATCH * NQ];

// monotone float<->uint encoding for atomicMax on floats (incl. negatives)
__device__ __forceinline__ unsigned fenc(float f) {
    unsigned u = __float_as_uint(f);
    return (u & 0x80000000u) ? ~u : (u | 0x80000000u);
}
__device__ __forceinline__ float fdec(unsigned e) {
    unsigned u = (e & 0x80000000u) ? (e & 0x7FFFFFFFu) : ~e;
    return __uint_as_float(u);
}

#define MMA_BF16(c0, c1, c2, c3, a0, a1, a2, a3, b0, b1) \
    asm volatile("mma.sync.aligned.m16n8k16.row.col.f32.bf16.bf16.f32 " \
        "{%0,%1,%2,%3}, {%4,%5,%6,%7}, {%8,%9}, {%0,%1,%2,%3};" \
        : "+f"(c0), "+f"(c1), "+f"(c2), "+f"(c3) \
        : "r"(a0), "r"(a1), "r"(a2), "r"(a3), "r"(b0), "r"(b1))

// -------- kernel 0: zero output + candidate counters --------
__global__ void zero_kernel(float4* out, int n4) {
    int i = blockIdx.x * blockDim.x + threadIdx.x;
    if (i < n4) out[i] = make_float4(0.f, 0.f, 0.f, 0.f);
    if (i < BATCH * NQ / 4) ((int4*)g_ccnt)[i] = make_int4(0, 0, 0, 0);
}

// -------- kernel 1: deterministic stream compaction of masks --------
__global__ void compact_kernel(const unsigned int* qmask, const unsigned int* mmask) {
    int b = blockIdx.x;
    int which = blockIdx.y;    // 0 = q, 1 = m
    const unsigned int* mask = which ? (mmask + b * NM) : (qmask + b * NQ);
    int n = which ? NM : NQ;
    int* list = which ? (g_mlist + b * NM) : (g_qlist + b * NQ);

    __shared__ int wcnt[NTHREADS / 32];
    __shared__ int sbase;
    int tid = threadIdx.x, lane = tid & 31, wid = tid >> 5;
    if (tid == 0) sbase = 0;
    __syncthreads();

    for (int start = 0; start < n; start += NTHREADS) {
        int idx = start + tid;
        int flag = (idx < n) && (mask[idx] != 0u);
        unsigned bal = __ballot_sync(0xFFFFFFFFu, flag);
        int pre = __popc(bal & ((1u << lane) - 1u));
        if (lane == 0) wcnt[wid] = __popc(bal);
        __syncthreads();
        int wbase = 0, tot = 0;
#pragma unroll
        for (int w = 0; w < NTHREADS / 32; w++) {
            if (w < wid) wbase += wcnt[w];
            tot += wcnt[w];
        }
        int base = sbase;
        if (flag) list[base + wbase + pre] = idx;
        __syncthreads();
        if (tid == 0) sbase = base + tot;
        __syncthreads();
    }
    if (tid == 0) {
        if (which) g_nm[b] = sbase; else g_nq[b] = sbase;
    }
}

// -------- kernel 2: gather-pack qkey/mkey into packed bf16x2 k-pair words --------
__global__ void pack_kernel(const float* qkey, const float* mkey) {
    int dp = blockIdx.x;                 // k-pair index, 0..63
    int b = blockIdx.y;
    int nq = g_nq[b], nm = g_nm[b];
    const float* qs0 = qkey + (size_t)(b * DK + 2 * dp) * NQ;
    const float* qs1 = qs0 + NQ;
    const float* ms0 = mkey + (size_t)(b * DK + 2 * dp) * NM;
    const float* ms1 = ms0 + NM;
    uint32_t* qd = g_qkb + (size_t)(b * (DK / 2) + dp) * NQ;
    uint32_t* md = g_mkb + (size_t)(b * (DK / 2) + dp) * NM;
    for (int i = threadIdx.x; i < NQ; i += blockDim.x) {
        float v0 = 0.f, v1 = 0.f;
        if (i < nq) { int g = g_qlist[b * NQ + i]; v0 = qs0[g]; v1 = qs1[g]; }
        __nv_bfloat162 w = __floats2bfloat162_rn(v0, v1);   // .x = v0 (low half = even k)
        qd[i] = *(uint32_t*)&w;
    }
    for (int i = threadIdx.x; i < NM; i += blockDim.x) {
        float v0 = 0.f, v1 = 0.f;
        if (i < nm) { int g = g_mlist[b * NM + i]; v0 = ms0[g]; v1 = ms1[g]; }
        __nv_bfloat162 w = __floats2bfloat162_rn(v0, v1);
        md[i] = *(uint32_t*)&w;
    }
}

// -------- kernel 2b: gather-transpose exact mkey -> g_mkT [b][m][d] --------
__global__ void transposeK_kernel(const float* __restrict__ mkey) {
    __shared__ float t[32][33];
    int b = blockIdx.z;
    int nm = g_nm[b];
    int m0 = blockIdx.x * 32, d0 = blockIdx.y * 32;
    if (m0 >= nm) return;
    int tx = threadIdx.x, ty = threadIdx.y;   // 32 x 8
    const float* src = mkey + (size_t)b * DK * NM;
    int mg = (m0 + tx < nm) ? g_mlist[b * NM + m0 + tx] : 0;
#pragma unroll
    for (int i = ty; i < 32; i += 8)
        t[tx][i] = src[(size_t)(d0 + i) * NM + mg];
    __syncthreads();
    float* dst = g_mkT + (size_t)b * NM * DK;
#pragma unroll
    for (int i = ty; i < 32; i += 8)
        if (m0 + i < nm)
            dst[(size_t)(m0 + i) * DK + d0 + tx] = t[i][tx];
}

// -------- kernel 3: bf16 mma.sync screening GEMM + candidate emission --------
__global__ __launch_bounds__(NTHREADS)
void qk_mma_kernel() {
    int b = blockIdx.z, seg = blockIdx.y;
    int nq = g_nq[b], nm = g_nm[b];
    int qi0 = blockIdx.x * QTILE;
    if (qi0 >= nq || nm == 0) return;
    int segsz = (((nm + NSEG - 1) / NSEG) + MC - 1) / MC * MC;
    int ms = seg * segsz;
    if (ms >= nm) return;
    int me = min(ms + segsz, nm);
    int nch = (me - ms + MC - 1) / MC;

    extern __shared__ char smem[];
    unsigned* sGMax = (unsigned*)(smem + SM_GMAX);
    uint32_t* sA = (uint32_t*)(smem + SM_A);

    int tid = threadIdx.x, lane = tid & 31, wid = tid >> 5;
    int gr = lane >> 2, tig = lane & 3;
    int warp_q0 = (wid >> 2) * 64;
    int warp_m0 = (wid & 3) * 32;

    if (tid < QTILE) sGMax[tid] = fenc(-3.0e38f);

    // stage A tile [kp=64][q=128] packed words
    const uint32_t* qkb = g_qkb + (size_t)b * (DK / 2) * NQ;
#pragma unroll
    for (int it = 0; it < 8; it++) {
        int idx = tid + it * NTHREADS;   // 2048 float4 slots
        int kp = idx >> 5, j = idx & 31;
        const uint32_t* src = &qkb[(size_t)kp * NQ + qi0 + j * 4];
        unsigned sa = (unsigned)__cvta_generic_to_shared(sA + kp * RS + j * 4);
        asm volatile("cp.async.cg.shared.global [%0], [%1], 16;" :: "r"(sa), "l"(src));
    }
    asm volatile("cp.async.commit_group;");

    const uint32_t* mkb = g_mkb + (size_t)b * (DK / 2) * NM;
    auto issueB = [&](int m0, int buf) {
        uint32_t* dst = (uint32_t*)(smem + SM_B) + buf * 64 * RS;
#pragma unroll
        for (int it = 0; it < 8; it++) {
            int idx = tid + it * NTHREADS;
            int kp = idx >> 5, j = idx & 31;
            const uint32_t* src = &mkb[(size_t)kp * NM + m0 + j * 4];
            unsigned sa = (unsigned)__cvta_generic_to_shared(dst + kp * RS + j * 4);
            asm volatile("cp.async.cg.shared.global [%0], [%1], 16;" :: "r"(sa), "l"(src));
        }
        asm volatile("cp.async.commit_group;");
    };

    issueB(ms, 0);

    for (int c = 0; c < nch; c++) {
        int mt0 = ms + c * MC;
        asm volatile("cp.async.wait_group 0;");
        __syncthreads();
        if (c + 1 < nch) issueB(ms + (c + 1) * MC, (c + 1) & 1);

        const uint32_t* sB = (const uint32_t*)(smem + SM_B) + (c & 1) * 64 * RS;

        float acc[4][4][4];
#pragma unroll
        for (int qf = 0; qf < 4; qf++)
#pragma unroll
            for (int nf = 0; nf < 4; nf++)
#pragma unroll
                for (int r = 0; r < 4; r++) acc[qf][nf][r] = 0.f;

        // K = 128 -> 8 steps of k=16 (8 kp rows per step)
#pragma unroll
        for (int s = 0; s < 8; s++) {
            const uint32_t* rAlo = sA + (s * 8 + tig) * RS;       // kp = s*8 + tig
            const uint32_t* rAhi = rAlo + 4 * RS;                 // kp + 4 (k+8)
            const uint32_t* rBlo = sB + (s * 8 + tig) * RS;
            const uint32_t* rBhi = rBlo + 4 * RS;
            uint32_t a[4][4], bb[4][2];
#pragma unroll
            for (int qf = 0; qf < 4; qf++) {
                int cq = warp_q0 + qf * 16 + gr;
                a[qf][0] = rAlo[cq];
                a[qf][1] = rAlo[cq + 8];
                a[qf][2] = rAhi[cq];
                a[qf][3] = rAhi[cq + 8];
            }
#pragma unroll
            for (int nf = 0; nf < 4; nf++) {
                int cn = warp_m0 + nf * 8 + gr;
                bb[nf][0] = rBlo[cn];
                bb[nf][1] = rBhi[cn];
            }
#pragma unroll
            for (int qf = 0; qf < 4; qf++)
#pragma unroll
                for (int nf = 0; nf < 4; nf++)
                    MMA_BF16(acc[qf][nf][0], acc[qf][nf][1], acc[qf][nf][2], acc[qf][nf][3],
                             a[qf][0], a[qf][1], a[qf][2], a[qf][3],
                             bb[nf][0], bb[nf][1]);
        }

        // epilogue: per q-row block max + rare candidate emission
        int mbw = mt0 + warp_m0;
#pragma unroll
        for (int qf = 0; qf < 4; qf++) {
#pragma unroll
            for (int h = 0; h < 2; h++) {
                int qrow = warp_q0 + qf * 16 + gr + h * 8;
                int q = qi0 + qrow;
                float sv[8];
                float bm = -3.0e38f;
#pragma unroll
                for (int nf = 0; nf < 4; nf++)
#pragma unroll
                    for (int col = 0; col < 2; col++) {
                        int ii = nf * 2 + col;
                        sv[ii] = acc[qf][nf][h * 2 + col] * PSCALAR;
                        int mg = mbw + nf * 8 + 2 * tig + col;
                        if (mg < me) bm = fmaxf(bm, sv[ii]);
                    }
                if (q < nq && bm > fdec(sGMax[qrow]) - DELTAS) {
                    unsigned olde = atomicMax(&sGMax[qrow], fenc(bm));
                    float th = fmaxf(fdec(olde), bm);
#pragma unroll
                    for (int nf = 0; nf < 4; nf++)
#pragma unroll
                        for (int col = 0; col < 2; col++) {
                            int ii = nf * 2 + col;
                            int mg = mbw + nf * 8 + 2 * tig + col;
                            if (mg < me && sv[ii] > th - DELTAS) {
                                int pos = atomicAdd(&g_ccnt[b * NQ + q], 1);
                                if (pos < CAP)
                                    g_cand[((size_t)b * NQ + q) * CAP + pos] =
                                        make_int2(mg, __float_as_int(sv[ii]));
                            }
                        }
                }
            }
        }
        __syncthreads();
    }
}

// -------- kernel 4: finalize — exact logits on deterministic set + softmax + gather --------
__global__ __launch_bounds__(NTHREADS)
void finalize_kernel(const float* __restrict__ qkey, const float* __restrict__ mval,
                     float* __restrict__ out) {
    __shared__ float sQc[8 * DK];
    int b = blockIdx.y;
    int nq = g_nq[b], nm = g_nm[b];
    int wid = threadIdx.x >> 5, lane = threadIdx.x & 31;
    int q = blockIdx.x * 8 + wid;
    if (nm == 0 || q >= nq) return;

    int qg = g_qlist[b * NQ + q];

    // load this warp's exact q column into smem (gather from original qkey)
    for (int d = lane; d < DK; d += 32)
        sQc[wid * DK + d] = qkey[(size_t)(b * DK + d) * NQ + qg];
    __syncwarp();

    size_t cbase = ((size_t)b * NQ + q) * CAP;
    int c = min(g_ccnt[b * NQ + q], CAP);

    // screened max (order-free) -> deterministic candidate filter
    float mxs = -3.0e38f;
    for (int i = lane; i < c; i += 32)
        mxs = fmaxf(mxs, __int_as_float(g_cand[cbase + i].y));
#pragma unroll
    for (int off = 16; off; off >>= 1)
        mxs = fmaxf(mxs, __shfl_xor_sync(0xFFFFFFFFu, mxs, off));

    // pass A: exact fp32 logits for kept candidates; write back (non-kept -> -inf)
    const float* mkT = g_mkT + (size_t)b * NM * DK;
    const float4* qc4 = (const float4*)&sQc[wid * DK];
    float mx = -3.0e38f;
    for (int i = lane; i < c; i += 32) {
        int2 e = g_cand[cbase + i];
        float snew = -3.0e38f;
        if (__int_as_float(e.y) > mxs - DELTAS) {
            const float4* row = (const float4*)(mkT + (size_t)e.x * DK);
            float a0 = 0.f, a1 = 0.f, a2 = 0.f, a3 = 0.f;
#pragma unroll
            for (int j = 0; j < DK / 4; j++) {
                float4 mv = row[j];
                float4 qv = qc4[j];
                a0 = fmaf(qv.x, mv.x, a0);
                a1 = fmaf(qv.y, mv.y, a1);
                a2 = fmaf(qv.z, mv.z, a2);
                a3 = fmaf(qv.w, mv.w, a3);
            }
            snew = ((a0 + a1) + (a2 + a3)) * PSCALAR;
            mx = fmaxf(mx, snew);
        }
        g_cand[cbase + i].y = __float_as_int(snew);
    }
    __threadfence_block();
    __syncwarp();
#pragma unroll
    for (int off = 16; off; off >>= 1)
        mx = fmaxf(mx, __shfl_xor_sync(0xFFFFFFFFu, mx, off));

    // pass B: deterministic fixed-point exp sum over kept set (exact logits)
    unsigned long long iacc = 0;
    for (int i = lane; i < c; i += 32) {
        float s = __int_as_float(g_cand[cbase + i].y);
        if (s > -1.0e37f) {
            float w = expf(s - mx);
            iacc += (unsigned long long)((double)w * 4503599627370496.0);  // 2^52
        }
    }
#pragma unroll
    for (int off = 16; off; off >>= 1)
        iacc += __shfl_xor_sync(0xFFFFFFFFu, iacc, off);
    double dsum = (double)iacc * (1.0 / 4503599627370496.0);
    float inv = (float)(1.0 / dsum);

    // pass C: extract kept events in ascending-m order, gather mval columns
    float ov[16];
#pragma unroll
    for (int j = 0; j < 16; j++) ov[j] = 0.f;

    const float* mvb = mval + (size_t)b * DV * NM;
    int last = -1;
    while (true) {
        int mym = 0x7FFFFFFF; float myw = 0.f;
        for (int i = lane; i < c; i += 32) {
            int2 e = g_cand[cbase + i];
            float s = __int_as_float(e.y);
            if (s > -1.0e37f && e.x > last && e.x < mym) {
                mym = e.x;
                myw = expf(s - mx);
            }
        }
#pragma unroll
        for (int off = 16; off; off >>= 1) {
            int om = __shfl_xor_sync(0xFFFFFFFFu, mym, off);
            float ow = __shfl_xor_sync(0xFFFFFFFFu, myw, off);
            if (om < mym) { mym = om; myw = ow; }
        }
        if (mym == 0x7FFFFFFF) break;
        int mg = g_mlist[b * NM + mym];
        const float* col = mvb + mg;
#pragma unroll
        for (int j = 0; j < 16; j++)
            ov[j] += myw * col[(size_t)(lane + 32 * j) * NM];
        last = mym;
    }

    float* ob = out + (size_t)b * DV * NQ + qg;
#pragma unroll
    for (int j = 0; j < 16; j++)
        ob[(size_t)(lane + 32 * j) * NQ] = ov[j] * inv;
}

// -------- launch --------
extern "C" void kernel_launch(void* const* d_in, const int* in_sizes, int n_in,
                              void* d_out, int out_size) {
    const float*        qkey  = (const float*)d_in[0];
    // d_in[1] = qval (unused by the reference math)
    const unsigned int* qmask = (const unsigned int*)d_in[2];
    const float*        mkey  = (const float*)d_in[3];
    const float*        mval  = (const float*)d_in[4];
    const unsigned int* mmask = (const unsigned int*)d_in[5];
    float* out = (float*)d_out;

    int n4 = BATCH * DV * NQ / 4;
    zero_kernel<<<(n4 + 255) / 256, 256>>>((float4*)out, n4);

    compact_kernel<<<dim3(BATCH, 2), NTHREADS>>>(qmask, mmask);

    pack_kernel<<<dim3(DK / 2, BATCH), NTHREADS>>>(qkey, mkey);

    transposeK_kernel<<<dim3(NM / 32, DK / 32, BATCH), dim3(32, 8)>>>(mkey);

    cudaFuncSetAttribute(qk_mma_kernel, cudaFuncAttributeMaxDynamicSharedMemorySize, SM_TOTAL);
    qk_mma_kernel<<<dim3(NQ / QTILE, NSEG, BATCH), NTHREADS, SM_TOTAL>>>();

    finalize_kernel<<<dim3(NQ / 8, BATCH), NTHREADS>>>(qkey, mval, out);
}

// round 7
// speedup vs baseline: 1.5118x; 1.0952x over previous
#include <cuda_runtime.h>
#include <cuda_bf16.h>
#include <cstdint>
#include <math.h>

// Problem shapes (fixed for this bench)
#define BATCH 2
#define DK 128
#define DV 512
#define NQ 4096         // H*W
#define NM 8192         // T*H*W
#define NTHREADS 256
#define PSCALAR 40.0f
// -ln(1e-12) + 8.0 slack for bf16 screening error (~11 sigma)
#define DELTAS 35.6310211159f

#define QTILE 128
#define MC 128
#define NSEG 4
#define CAP 1024
#define FCAND 64         // smem-cached candidates per q in finalize
#define RS 136           // smem row stride in 32-bit words (conflict-free)

// smem byte offsets (qk_mma)
#define SM_GMAX  0
#define SM_A     512                              // 64 rows x RS words
#define SM_B     (512 + 64 * RS * 4)              // 2 bufs x 64 x RS words
#define SM_TOTAL (SM_B + 2 * 64 * RS * 4)         // 104960 B

typedef unsigned long long ull;

// -------- device scratch (static: no allocations allowed) --------
__device__ uint32_t g_qkb[BATCH * (DK / 2) * NQ];   // packed bf16x2 (k-pair) [b][dp][q]
__device__ uint32_t g_mkb[BATCH * (DK / 2) * NM];   // packed bf16x2 (k-pair) [b][dp][m]
__device__ int      g_qlist[BATCH * NQ];
__device__ int      g_mlist[BATCH * NM];
__device__ int      g_nq[BATCH];
__device__ int      g_nm[BATCH];
__device__ int2     g_cand[(size_t)BATCH * NQ * CAP];  // (m_compact, logit bits)
__device__ int      g_ccnt[BATCH * NQ];

// monotone float<->uint encoding for atomicMax on floats (incl. negatives)
__device__ __forceinline__ unsigned fenc(float f) {
    unsigned u = __float_as_uint(f);
    return (u & 0x80000000u) ? ~u : (u | 0x80000000u);
}
__device__ __forceinline__ float fdec(unsigned e) {
    unsigned u = (e & 0x80000000u) ? (e & 0x7FFFFFFFu) : ~e;
    return __uint_as_float(u);
}

#define MMA_BF16(c0, c1, c2, c3, a0, a1, a2, a3, b0, b1) \
    asm volatile("mma.sync.aligned.m16n8k16.row.col.f32.bf16.bf16.f32 " \
        "{%0,%1,%2,%3}, {%4,%5,%6,%7}, {%8,%9}, {%0,%1,%2,%3};" \
        : "+f"(c0), "+f"(c1), "+f"(c2), "+f"(c3) \
        : "r"(a0), "r"(a1), "r"(a2), "r"(a3), "r"(b0), "r"(b1))

// -------- kernel 0: zero output + candidate counters --------
__global__ void zero_kernel(float4* out, int n4) {
    int i = blockIdx.x * blockDim.x + threadIdx.x;
    if (i < n4) out[i] = make_float4(0.f, 0.f, 0.f, 0.f);
    if (i < BATCH * NQ / 4) ((int4*)g_ccnt)[i] = make_int4(0, 0, 0, 0);
}

// -------- kernel 1: deterministic stream compaction of masks --------
__global__ void compact_kernel(const unsigned int* qmask, const unsigned int* mmask) {
    int b = blockIdx.x;
    int which = blockIdx.y;    // 0 = q, 1 = m
    const unsigned int* mask = which ? (mmask + b * NM) : (qmask + b * NQ);
    int n = which ? NM : NQ;
    int* list = which ? (g_mlist + b * NM) : (g_qlist + b * NQ);

    __shared__ int wcnt[NTHREADS / 32];
    __shared__ int sbase;
    int tid = threadIdx.x, lane = tid & 31, wid = tid >> 5;
    if (tid == 0) sbase = 0;
    __syncthreads();

    for (int start = 0; start < n; start += NTHREADS) {
        int idx = start + tid;
        int flag = (idx < n) && (mask[idx] != 0u);
        unsigned bal = __ballot_sync(0xFFFFFFFFu, flag);
        int pre = __popc(bal & ((1u << lane) - 1u));
        if (lane == 0) wcnt[wid] = __popc(bal);
        __syncthreads();
        int wbase = 0, tot = 0;
#pragma unroll
        for (int w = 0; w < NTHREADS / 32; w++) {
            if (w < wid) wbase += wcnt[w];
            tot += wcnt[w];
        }
        int base = sbase;
        if (flag) list[base + wbase + pre] = idx;
        __syncthreads();
        if (tid == 0) sbase = base + tot;
        __syncthreads();
    }
    if (tid == 0) {
        if (which) g_nm[b] = sbase; else g_nq[b] = sbase;
    }
}

// -------- kernel 2: gather-pack qkey/mkey into packed bf16x2 k-pair words --------
__global__ void pack_kernel(const float* qkey, const float* mkey) {
    int dp = blockIdx.x;                 // k-pair index, 0..63
    int b = blockIdx.y;
    int nq = g_nq[b], nm = g_nm[b];
    const float* qs0 = qkey + (size_t)(b * DK + 2 * dp) * NQ;
    const float* qs1 = qs0 + NQ;
    const float* ms0 = mkey + (size_t)(b * DK + 2 * dp) * NM;
    const float* ms1 = ms0 + NM;
    uint32_t* qd = g_qkb + (size_t)(b * (DK / 2) + dp) * NQ;
    uint32_t* md = g_mkb + (size_t)(b * (DK / 2) + dp) * NM;
    for (int i = threadIdx.x; i < NQ; i += blockDim.x) {
        float v0 = 0.f, v1 = 0.f;
        if (i < nq) { int g = g_qlist[b * NQ + i]; v0 = qs0[g]; v1 = qs1[g]; }
        __nv_bfloat162 w = __floats2bfloat162_rn(v0, v1);   // .x = v0 (low half = even k)
        qd[i] = *(uint32_t*)&w;
    }
    for (int i = threadIdx.x; i < NM; i += blockDim.x) {
        float v0 = 0.f, v1 = 0.f;
        if (i < nm) { int g = g_mlist[b * NM + i]; v0 = ms0[g]; v1 = ms1[g]; }
        __nv_bfloat162 w = __floats2bfloat162_rn(v0, v1);
        md[i] = *(uint32_t*)&w;
    }
}

// -------- kernel 3: bf16 mma.sync screening GEMM + candidate emission --------
__global__ __launch_bounds__(NTHREADS)
void qk_mma_kernel() {
    int b = blockIdx.z, seg = blockIdx.y;
    int nq = g_nq[b], nm = g_nm[b];
    int qi0 = blockIdx.x * QTILE;
    if (qi0 >= nq || nm == 0) return;
    int segsz = (((nm + NSEG - 1) / NSEG) + MC - 1) / MC * MC;
    int ms = seg * segsz;
    if (ms >= nm) return;
    int me = min(ms + segsz, nm);
    int nch = (me - ms + MC - 1) / MC;

    extern __shared__ char smem[];
    unsigned* sGMax = (unsigned*)(smem + SM_GMAX);
    uint32_t* sA = (uint32_t*)(smem + SM_A);

    int tid = threadIdx.x, lane = tid & 31, wid = tid >> 5;
    int gr = lane >> 2, tig = lane & 3;
    int warp_q0 = (wid >> 2) * 64;
    int warp_m0 = (wid & 3) * 32;

    if (tid < QTILE) sGMax[tid] = fenc(-3.0e38f);

    // stage A tile [kp=64][q=128] packed words
    const uint32_t* qkb = g_qkb + (size_t)b * (DK / 2) * NQ;
#pragma unroll
    for (int it = 0; it < 8; it++) {
        int idx = tid + it * NTHREADS;   // 2048 float4 slots
        int kp = idx >> 5, j = idx & 31;
        const uint32_t* src = &qkb[(size_t)kp * NQ + qi0 + j * 4];
        unsigned sa = (unsigned)__cvta_generic_to_shared(sA + kp * RS + j * 4);
        asm volatile("cp.async.cg.shared.global [%0], [%1], 16;" :: "r"(sa), "l"(src));
    }
    asm volatile("cp.async.commit_group;");

    const uint32_t* mkb = g_mkb + (size_t)b * (DK / 2) * NM;
    auto issueB = [&](int m0, int buf) {
        uint32_t* dst = (uint32_t*)(smem + SM_B) + buf * 64 * RS;
#pragma unroll
        for (int it = 0; it < 8; it++) {
            int idx = tid + it * NTHREADS;
            int kp = idx >> 5, j = idx & 31;
            const uint32_t* src = &mkb[(size_t)kp * NM + m0 + j * 4];
            unsigned sa = (unsigned)__cvta_generic_to_shared(dst + kp * RS + j * 4);
            asm volatile("cp.async.cg.shared.global [%0], [%1], 16;" :: "r"(sa), "l"(src));
        }
        asm volatile("cp.async.commit_group;");
    };

    issueB(ms, 0);

    for (int c = 0; c < nch; c++) {
        int mt0 = ms + c * MC;
        asm volatile("cp.async.wait_group 0;");
        __syncthreads();
        if (c + 1 < nch) issueB(ms + (c + 1) * MC, (c + 1) & 1);

        const uint32_t* sB = (const uint32_t*)(smem + SM_B) + (c & 1) * 64 * RS;

        float acc[4][4][4];
#pragma unroll
        for (int qf = 0; qf < 4; qf++)
#pragma unroll
            for (int nf = 0; nf < 4; nf++)
#pragma unroll
                for (int r = 0; r < 4; r++) acc[qf][nf][r] = 0.f;

        // K = 128 -> 8 steps of k=16 (8 kp rows per step)
#pragma unroll
        for (int s = 0; s < 8; s++) {
            const uint32_t* rAlo = sA + (s * 8 + tig) * RS;       // kp = s*8 + tig
            const uint32_t* rAhi = rAlo + 4 * RS;                 // kp + 4 (k+8)
            const uint32_t* rBlo = sB + (s * 8 + tig) * RS;
            const uint32_t* rBhi = rBlo + 4 * RS;
            uint32_t a[4][4], bb[4][2];
#pragma unroll
            for (int qf = 0; qf < 4; qf++) {
                int cq = warp_q0 + qf * 16 + gr;
                a[qf][0] = rAlo[cq];
                a[qf][1] = rAlo[cq + 8];
                a[qf][2] = rAhi[cq];
                a[qf][3] = rAhi[cq + 8];
            }
#pragma unroll
            for (int nf = 0; nf < 4; nf++) {
                int cn = warp_m0 + nf * 8 + gr;
                bb[nf][0] = rBlo[cn];
                bb[nf][1] = rBhi[cn];
            }
#pragma unroll
            for (int qf = 0; qf < 4; qf++)
#pragma unroll
                for (int nf = 0; nf < 4; nf++)
                    MMA_BF16(acc[qf][nf][0], acc[qf][nf][1], acc[qf][nf][2], acc[qf][nf][3],
                             a[qf][0], a[qf][1], a[qf][2], a[qf][3],
                             bb[nf][0], bb[nf][1]);
        }

        // epilogue: per q-row block max + rare candidate emission
        int mbw = mt0 + warp_m0;
#pragma unroll
        for (int qf = 0; qf < 4; qf++) {
#pragma unroll
            for (int h = 0; h < 2; h++) {
                int qrow = warp_q0 + qf * 16 + gr + h * 8;
                int q = qi0 + qrow;
                float sv[8];
                float bm = -3.0e38f;
#pragma unroll
                for (int nf = 0; nf < 4; nf++)
#pragma unroll
                    for (int col = 0; col < 2; col++) {
                        int ii = nf * 2 + col;
                        sv[ii] = acc[qf][nf][h * 2 + col] * PSCALAR;
                        int mg = mbw + nf * 8 + 2 * tig + col;
                        if (mg < me) bm = fmaxf(bm, sv[ii]);
                    }
                if (q < nq && bm > fdec(sGMax[qrow]) - DELTAS) {
                    unsigned olde = atomicMax(&sGMax[qrow], fenc(bm));
                    float th = fmaxf(fdec(olde), bm);
#pragma unroll
                    for (int nf = 0; nf < 4; nf++)
#pragma unroll
                        for (int col = 0; col < 2; col++) {
                            int ii = nf * 2 + col;
                            int mg = mbw + nf * 8 + 2 * tig + col;
                            if (mg < me && sv[ii] > th - DELTAS) {
                                int pos = atomicAdd(&g_ccnt[b * NQ + q], 1);
                                if (pos < CAP)
                                    g_cand[((size_t)b * NQ + q) * CAP + pos] =
                                        make_int2(mg, __float_as_int(sv[ii]));
                            }
                        }
                }
            }
        }
        __syncthreads();
    }
}

// -------- kernel 4: finalize — exact logits (direct mkey columns) + softmax + gather --------
__global__ __launch_bounds__(NTHREADS)
void finalize_kernel(const float* __restrict__ qkey, const float* __restrict__ mkey,
                     const float* __restrict__ mval, float* __restrict__ out) {
    __shared__ float sQc[8 * DK];            // 4 KB
    __shared__ int2  sCand[8][FCAND];        // 4 KB
    __shared__ float sO[8][DV + 4];          // 16.1 KB
    __shared__ int   sQg[8];
    int b = blockIdx.y;
    int nq = g_nq[b], nm = g_nm[b];
    if (nm == 0) return;                     // uniform across block
    int tid = threadIdx.x, wid = tid >> 5, lane = tid & 31;
    int q = blockIdx.x * 8 + wid;
    bool valid = (q < nq);

    int qg = 0, c = 0;
    size_t cbase = 0;
    if (valid) {
        qg = g_qlist[b * NQ + q];
        cbase = ((size_t)b * NQ + q) * CAP;
        c = min(g_ccnt[b * NQ + q], CAP);
    }
    if (lane == 0) sQg[wid] = valid ? qg : -1;

    if (valid) {
        // exact q column into smem
        for (int d = lane; d < DK; d += 32)
            sQc[wid * DK + d] = qkey[(size_t)(b * DK + d) * NQ + qg];
        // cache candidates in smem
        for (int i = lane; i < c && i < FCAND; i += 32)
            sCand[wid][i] = g_cand[cbase + i];
    }
    __syncwarp();

    float inv = 0.f, mx = -3.0e38f;
    if (valid) {
        // screened max (order-free)
        float mxs = -3.0e38f;
        for (int i = lane; i < c; i += 32) {
            int2 e = (i < FCAND) ? sCand[wid][i] : g_cand[cbase + i];
            mxs = fmaxf(mxs, __int_as_float(e.y));
        }
#pragma unroll
        for (int off = 16; off; off >>= 1)
            mxs = fmaxf(mxs, __shfl_xor_sync(0xFFFFFFFFu, mxs, off));

        // pass A: exact fp32 logit per kept candidate (warp-cooperative dot on mkey column)
        const float* mkb = mkey + (size_t)b * DK * NM;
        for (int i = 0; i < c; i++) {
            int2 e = (i < FCAND) ? sCand[wid][i] : g_cand[cbase + i];
            float snew = -3.0e38f;
            if (__int_as_float(e.y) > mxs - DELTAS) {
                int mg = g_mlist[b * NM + e.x];
                const float* mcol = mkb + mg;
                float part = 0.f;
#pragma unroll
                for (int r = 0; r < DK / 32; r++) {
                    int d = lane + r * 32;
                    part = fmaf(sQc[wid * DK + d], mcol[(size_t)d * NM], part);
                }
#pragma unroll
                for (int off = 16; off; off >>= 1)
                    part += __shfl_xor_sync(0xFFFFFFFFu, part, off);
                snew = part * PSCALAR;
                mx = fmaxf(mx, snew);
            }
            if (lane == 0) {
                if (i < FCAND) sCand[wid][i].y = __float_as_int(snew);
                else g_cand[cbase + i].y = __float_as_int(snew);
            }
        }
        __syncwarp();

        // pass B: deterministic fixed-point exp sum over kept set (exact logits)
        unsigned long long iacc = 0;
        for (int i = lane; i < c; i += 32) {
            float s = __int_as_float((i < FCAND) ? sCand[wid][i].y : g_cand[cbase + i].y);
            if (s > -1.0e37f) {
                float w = expf(s - mx);
                iacc += (unsigned long long)((double)w * 4503599627370496.0);  // 2^52
            }
        }
#pragma unroll
        for (int off = 16; off; off >>= 1)
            iacc += __shfl_xor_sync(0xFFFFFFFFu, iacc, off);
        double dsum = (double)iacc * (1.0 / 4503599627370496.0);
        inv = (float)(1.0 / dsum);

        // pass C: extract kept events in ascending-m order, gather mval columns
        float ov[16];
#pragma unroll
        for (int j = 0; j < 16; j++) ov[j] = 0.f;

        const float* mvb = mval + (size_t)b * DV * NM;
        int last = -1;
        while (true) {
            int mym = 0x7FFFFFFF; float myw = 0.f;
            for (int i = lane; i < c; i += 32) {
                int2 e = (i < FCAND) ? sCand[wid][i] : g_cand[cbase + i];
                float s = __int_as_float(e.y);
                if (s > -1.0e37f && e.x > last && e.x < mym) {
                    mym = e.x;
                    myw = expf(s - mx);
                }
            }
#pragma unroll
            for (int off = 16; off; off >>= 1) {
                int om = __shfl_xor_sync(0xFFFFFFFFu, mym, off);
                float ow = __shfl_xor_sync(0xFFFFFFFFu, myw, off);
                if (om < mym) { mym = om; myw = ow; }
            }
            if (mym == 0x7FFFFFFF) break;
            int mg = g_mlist[b * NM + mym];
            const float* col = mvb + mg;
#pragma unroll
            for (int j = 0; j < 16; j++)
                ov[j] += myw * col[(size_t)(lane + 32 * j) * NM];
            last = mym;
        }

        // stage normalized output to smem
#pragma unroll
        for (int j = 0; j < 16; j++)
            sO[wid][lane + 32 * j] = ov[j] * inv;
    }
    __syncthreads();

    // coalesced-ish write: consecutive threads cover the 8 q's of one v
    float* ob = out + (size_t)b * DV * NQ;
    for (int idx = tid; idx < 8 * DV; idx += NTHREADS) {
        int v = idx >> 3, k = idx & 7;
        int qgk = sQg[k];
        if (qgk >= 0) ob[(size_t)v * NQ + qgk] = sO[k][v];
    }
}

// -------- launch --------
extern "C" void kernel_launch(void* const* d_in, const int* in_sizes, int n_in,
                              void* d_out, int out_size) {
    const float*        qkey  = (const float*)d_in[0];
    // d_in[1] = qval (unused by the reference math)
    const unsigned int* qmask = (const unsigned int*)d_in[2];
    const float*        mkey  = (const float*)d_in[3];
    const float*        mval  = (const float*)d_in[4];
    const unsigned int* mmask = (const unsigned int*)d_in[5];
    float* out = (float*)d_out;

    int n4 = BATCH * DV * NQ / 4;
    zero_kernel<<<(n4 + 255) / 256, 256>>>((float4*)out, n4);

    compact_kernel<<<dim3(BATCH, 2), NTHREADS>>>(qmask, mmask);

    pack_kernel<<<dim3(DK / 2, BATCH), NTHREADS>>>(qkey, mkey);

    // launch #4 — ncu's fixed capture slot: this is the kernel we need profiled
    cudaFuncSetAttribute(qk_mma_kernel, cudaFuncAttributeMaxDynamicSharedMemorySize, SM_TOTAL);
    qk_mma_kernel<<<dim3(NQ / QTILE, NSEG, BATCH), NTHREADS, SM_TOTAL>>>();

    finalize_kernel<<<dim3(NQ / 8, BATCH), NTHREADS>>>(qkey, mkey, mval, out);
}

// round 10
// speedup vs baseline: 1.9175x; 1.2683x over previous
#include <cuda_runtime.h>
#include <cuda_bf16.h>
#include <cstdint>
#include <math.h>

// Problem shapes (fixed for this bench)
#define BATCH 2
#define DK 128
#define DV 512
#define NQ 4096         // H*W
#define NM 8192         // T*H*W
#define NTHREADS 256
#define PSCALAR 40.0f
// -ln(1e-12) + 8.0 slack for bf16 screening error (~11 sigma)
#define DELTAS 35.6310211159f

#define QTILE 128
#define MC 128
#define NSEG 8
#define GRIDX 296
#define CAP 1024
#define FCAND 64

// qk smem layout (bytes): row-major bf16x2 tiles, 256B rows (64 words), XOR-swizzled
#define SMQ_A 512
#define SMQ_B (512 + 32768)
#define SMQ_TOTAL (SMQ_B + 2 * 32768)   // 98816 B -> 2 CTAs/SM

typedef unsigned long long ull;

// -------- device scratch (static: no allocations allowed) --------
__device__ uint32_t g_qkr[(size_t)BATCH * NQ * 64];   // packed bf16x2 rows [b][q][kp]
__device__ uint32_t g_mkr[(size_t)BATCH * NM * 64];   // packed bf16x2 rows [b][m][kp]
__device__ int      g_qlist[BATCH * NQ];
__device__ int      g_mlist[BATCH * NM];
__device__ int      g_nq[BATCH];
__device__ int      g_nm[BATCH];
__device__ int2     g_cand[(size_t)BATCH * NQ * CAP];  // (m_compact, logit bits)
__device__ int      g_ccnt[BATCH * NQ];

// monotone float<->uint encoding for atomicMax on floats (incl. negatives)
__device__ __forceinline__ unsigned fenc(float f) {
    unsigned u = __float_as_uint(f);
    return (u & 0x80000000u) ? ~u : (u | 0x80000000u);
}
__device__ __forceinline__ float fdec(unsigned e) {
    unsigned u = (e & 0x80000000u) ? (e & 0x7FFFFFFFu) : ~e;
    return __uint_as_float(u);
}
__device__ __forceinline__ uint32_t smem_u32(const void* p) {
    uint32_t a;
    asm("{ .reg .u64 t; cvta.to.shared.u64 t, %1; cvt.u32.u64 %0, t; }" : "=r"(a) : "l"(p));
    return a;
}

#define MMA_BF16(c0, c1, c2, c3, a0, a1, a2, a3, b0, b1) \
    asm volatile("mma.sync.aligned.m16n8k16.row.col.f32.bf16.bf16.f32 " \
        "{%0,%1,%2,%3}, {%4,%5,%6,%7}, {%8,%9}, {%0,%1,%2,%3};" \
        : "+f"(c0), "+f"(c1), "+f"(c2), "+f"(c3) \
        : "r"(a0), "r"(a1), "r"(a2), "r"(a3), "r"(b0), "r"(b1))

#define LDSM_X4(r0, r1, r2, r3, addr) \
    asm volatile("ldmatrix.sync.aligned.m8n8.x4.shared.b16 {%0,%1,%2,%3}, [%4];" \
        : "=r"(r0), "=r"(r1), "=r"(r2), "=r"(r3) : "r"(addr))

// -------- kernel 0: zero output + candidate counters --------
__global__ void zero_kernel(float4* out, int n4) {
    int i = blockIdx.x * blockDim.x + threadIdx.x;
    if (i < n4) out[i] = make_float4(0.f, 0.f, 0.f, 0.f);
    if (i < BATCH * NQ / 4) ((int4*)g_ccnt)[i] = make_int4(0, 0, 0, 0);
}

// -------- kernel 1: deterministic stream compaction of masks --------
__global__ void compact_kernel(const unsigned int* qmask, const unsigned int* mmask) {
    int b = blockIdx.x;
    int which = blockIdx.y;    // 0 = q, 1 = m
    const unsigned int* mask = which ? (mmask + b * NM) : (qmask + b * NQ);
    int n = which ? NM : NQ;
    int* list = which ? (g_mlist + b * NM) : (g_qlist + b * NQ);

    __shared__ int wcnt[NTHREADS / 32];
    __shared__ int sbase;
    int tid = threadIdx.x, lane = tid & 31, wid = tid >> 5;
    if (tid == 0) sbase = 0;
    __syncthreads();

    for (int start = 0; start < n; start += NTHREADS) {
        int idx = start + tid;
        int flag = (idx < n) && (mask[idx] != 0u);
        unsigned bal = __ballot_sync(0xFFFFFFFFu, flag);
        int pre = __popc(bal & ((1u << lane) - 1u));
        if (lane == 0) wcnt[wid] = __popc(bal);
        __syncthreads();
        int wbase = 0, tot = 0;
#pragma unroll
        for (int w = 0; w < NTHREADS / 32; w++) {
            if (w < wid) wbase += wcnt[w];
            tot += wcnt[w];
        }
        int base = sbase;
        if (flag) list[base + wbase + pre] = idx;
        __syncthreads();
        if (tid == 0) sbase = base + tot;
        __syncthreads();
    }
    if (tid == 0) {
        if (which) g_nm[b] = sbase; else g_nq[b] = sbase;
    }
}

// -------- kernel 2: gather-transpose-pack into bf16x2 row-major tiles --------
// Output row i (compacted index): 64 words, word kp = bf16x2(key[2kp], key[2kp+1])
__global__ void pack_kernel(const float* __restrict__ qkey, const float* __restrict__ mkey) {
    __shared__ float t[32][66];   // 66: keeps every row 8B-aligned (264B stride)
    int rb = blockIdx.x;          // 32-row block over (q rows ++ m rows)
    int half = blockIdx.y;        // d half: 0 -> d 0..63, 1 -> d 64..127
    int b = blockIdx.z;
    bool isq = rb < (NQ / 32);
    int base = isq ? rb * 32 : (rb - NQ / 32) * 32;
    int n = isq ? g_nq[b] : g_nm[b];
    int N = isq ? NQ : NM;
    const int* list = (isq ? g_qlist : g_mlist) + b * N;
    const float* src = (isq ? qkey : mkey) + (size_t)(b * DK + half * 64) * N;
    uint32_t* dst = (isq ? g_qkr : g_mkr) + ((size_t)b * N + base) * 64 + half * 32;

    int tx = threadIdx.x, ty = threadIdx.y;   // 32 x 8
    int i = base + tx;
    int g = (i < n) ? list[i] : -1;
#pragma unroll
    for (int dd = ty; dd < 64; dd += 8)
        t[tx][dd] = (g >= 0) ? src[(size_t)dd * N + g] : 0.f;
    __syncthreads();
#pragma unroll
    for (int mi = ty; mi < 32; mi += 8) {
        float2 v = *(float2*)&t[mi][2 * tx];
        __nv_bfloat162 w = __floats2bfloat162_rn(v.x, v.y);
        dst[(size_t)mi * 64 + tx] = *(uint32_t*)&w;
    }
}

// -------- kernel 3: bf16 mma.sync screening GEMM (ldmatrix, persistent items) --------
__global__ __launch_bounds__(NTHREADS, 2)
void qk_mma_kernel() {
    extern __shared__ char smem[];
    uint32_t sbase = smem_u32(smem);
    unsigned* sGMax = (unsigned*)smem;
    uint32_t sAu = sbase + SMQ_A, sBu = sbase + SMQ_B;

    int tid = threadIdx.x, lane = tid & 31, wid = tid >> 5;
    int gr = lane >> 2, tig = lane & 3;
    int warp_q0 = (wid >> 2) * 64;
    int warp_m0 = (wid & 3) * 32;

    int nt0 = (g_nm[0] > 0) ? ((g_nq[0] + 127) >> 7) : 0;
    int nt1 = (g_nm[1] > 0) ? ((g_nq[1] + 127) >> 7) : 0;
    int total = (nt0 + nt1) * NSEG;

    // per-lane ldmatrix row/koffset components
    int a_row_off = (lane & 15);
    int a_k16 = (lane >> 4) << 4;                      // 0 or 16 bytes
    int b_row_off = (lane & 7) + ((lane & 16) >> 1);   // +8 rows for lanes 16-31
    int b_k16 = (lane & 8) << 1;                       // 0 or 16 bytes

    for (int item = blockIdx.x; item < total; item += gridDim.x) {
        int tq = item / NSEG, seg = item - tq * NSEG;
        int b = (tq < nt0) ? 0 : 1;
        int qt = (tq < nt0) ? tq : tq - nt0;
        int nq = g_nq[b], nm = g_nm[b];
        int qi0 = qt * QTILE;
        int segsz = ((((nm + NSEG - 1) / NSEG) + MC - 1) / MC) * MC;
        int ms = seg * segsz;
        if (ms >= nm) continue;
        int me = min(ms + segsz, nm);
        int nch = (me - ms + MC - 1) / MC;

        if (tid < QTILE) sGMax[tid] = fenc(-3.0e38f);

        // stage A tile: 128 rows x 256B = 2048 16B chunks, swizzled
        {
            const uint32_t* arows = g_qkr + ((size_t)b * NQ + qi0) * 64;
#pragma unroll
            for (int k2 = 0; k2 < 8; k2++) {
                int idx = tid + k2 * NTHREADS;   // 2048 16B chunks
                int row = idx >> 4, ch = idx & 15;
                uint32_t doff = (uint32_t)((row << 8) + (ch << 4));
                doff ^= (uint32_t)((row & 7) << 4);
                const uint32_t* src = arows + row * 64 + ch * 4;
                asm volatile("cp.async.cg.shared.global [%0], [%1], 16;"
                             :: "r"(sAu + doff), "l"(src));
            }
            asm volatile("cp.async.commit_group;");
        }

        auto issueB = [&](int m0, int buf) {
            const uint32_t* brows = g_mkr + ((size_t)b * NM + m0) * 64;
            uint32_t bb = sBu + buf * 32768;
#pragma unroll
            for (int k2 = 0; k2 < 8; k2++) {
                int idx = tid + k2 * NTHREADS;   // 2048 16B chunks
                int row = idx >> 4, ch = idx & 15;
                uint32_t doff = (uint32_t)((row << 8) + (ch << 4));
                doff ^= (uint32_t)((row & 7) << 4);
                const uint32_t* src = brows + row * 64 + ch * 4;
                asm volatile("cp.async.cg.shared.global [%0], [%1], 16;"
                             :: "r"(bb + doff), "l"(src));
            }
            asm volatile("cp.async.commit_group;");
        };

        issueB(ms, 0);

        for (int c = 0; c < nch; c++) {
            int mt0 = ms + c * MC;
            asm volatile("cp.async.wait_group 0;");
            __syncthreads();
            if (c + 1 < nch) issueB(ms + (c + 1) * MC, (c + 1) & 1);

            uint32_t sBc = sBu + (c & 1) * 32768;

            float acc[4][4][4];
#pragma unroll
            for (int qf = 0; qf < 4; qf++)
#pragma unroll
                for (int nf = 0; nf < 4; nf++)
#pragma unroll
                    for (int r = 0; r < 4; r++) acc[qf][nf][r] = 0.f;

#pragma unroll
            for (int s = 0; s < 8; s++) {
                uint32_t a[4][4], bf[2][4];
#pragma unroll
                for (int qf = 0; qf < 4; qf++) {
                    int row = warp_q0 + qf * 16 + a_row_off;
                    uint32_t off = (uint32_t)((row << 8) + (s << 5) + a_k16)
                                 ^ (uint32_t)((row & 7) << 4);
                    LDSM_X4(a[qf][0], a[qf][1], a[qf][2], a[qf][3], sAu + off);
                }
#pragma unroll
                for (int np = 0; np < 2; np++) {
                    int row = warp_m0 + np * 16 + b_row_off;
                    uint32_t off = (uint32_t)((row << 8) + (s << 5) + b_k16)
                                 ^ (uint32_t)((row & 7) << 4);
                    LDSM_X4(bf[np][0], bf[np][1], bf[np][2], bf[np][3], sBc + off);
                }
#pragma unroll
                for (int qf = 0; qf < 4; qf++)
#pragma unroll
                    for (int nf = 0; nf < 4; nf++)
                        MMA_BF16(acc[qf][nf][0], acc[qf][nf][1], acc[qf][nf][2], acc[qf][nf][3],
                                 a[qf][0], a[qf][1], a[qf][2], a[qf][3],
                                 bf[nf >> 1][(nf & 1) * 2], bf[nf >> 1][(nf & 1) * 2 + 1]);
            }

            // epilogue: per q-row block max + rare candidate emission
            int mbw = mt0 + warp_m0;
#pragma unroll
            for (int qf = 0; qf < 4; qf++) {
#pragma unroll
                for (int h = 0; h < 2; h++) {
                    int qrow = warp_q0 + qf * 16 + gr + h * 8;
                    int q = qi0 + qrow;
                    float sv[8];
                    float bm = -3.0e38f;
#pragma unroll
                    for (int nf = 0; nf < 4; nf++)
#pragma unroll
                        for (int col = 0; col < 2; col++) {
                            int ii = nf * 2 + col;
                            sv[ii] = acc[qf][nf][h * 2 + col] * PSCALAR;
                            int mg = mbw + nf * 8 + 2 * tig + col;
                            if (mg < me) bm = fmaxf(bm, sv[ii]);
                        }
                    if (q < nq && bm > fdec(sGMax[qrow]) - DELTAS) {
                        unsigned olde = atomicMax(&sGMax[qrow], fenc(bm));
                        float th = fmaxf(fdec(olde), bm);
#pragma unroll
                        for (int nf = 0; nf < 4; nf++)
#pragma unroll
                            for (int col = 0; col < 2; col++) {
                                int ii = nf * 2 + col;
                                int mg = mbw + nf * 8 + 2 * tig + col;
                                if (mg < me && sv[ii] > th - DELTAS) {
                                    int pos = atomicAdd(&g_ccnt[b * NQ + q], 1);
                                    if (pos < CAP)
                                        g_cand[((size_t)b * NQ + q) * CAP + pos] =
                                            make_int2(mg, __float_as_int(sv[ii]));
                                }
                            }
                    }
                }
            }
            __syncthreads();
        }
    }
}

// -------- kernel 4: finalize — exact logits (direct mkey columns) + softmax + gather --------
__global__ __launch_bounds__(NTHREADS)
void finalize_kernel(const float* __restrict__ qkey, const float* __restrict__ mkey,
                     const float* __restrict__ mval, float* __restrict__ out) {
    __shared__ float sQc[8 * DK];            // 4 KB
    __shared__ int2  sCand[8][FCAND];        // 4 KB
    __shared__ float sO[8][DV + 4];          // 16.1 KB
    __shared__ int   sQg[8];
    int b = blockIdx.y;
    int nq = g_nq[b], nm = g_nm[b];
    if (nm == 0) return;                     // uniform across block
    int tid = threadIdx.x, wid = tid >> 5, lane = tid & 31;
    int q = blockIdx.x * 8 + wid;
    bool valid = (q < nq);

    int qg = 0, c = 0;
    size_t cbase = 0;
    if (valid) {
        qg = g_qlist[b * NQ + q];
        cbase = ((size_t)b * NQ + q) * CAP;
        c = min(g_ccnt[b * NQ + q], CAP);
    }
    if (lane == 0) sQg[wid] = valid ? qg : -1;

    if (valid) {
        for (int d = lane; d < DK; d += 32)
            sQc[wid * DK + d] = qkey[(size_t)(b * DK + d) * NQ + qg];
        for (int i = lane; i < c && i < FCAND; i += 32)
            sCand[wid][i] = g_cand[cbase + i];
    }
    __syncwarp();

    float inv = 0.f, mx = -3.0e38f;
    if (valid) {
        // screened max (order-free)
        float mxs = -3.0e38f;
        for (int i = lane; i < c; i += 32) {
            int2 e = (i < FCAND) ? sCand[wid][i] : g_cand[cbase + i];
            mxs = fmaxf(mxs, __int_as_float(e.y));
        }
#pragma unroll
        for (int off = 16; off; off >>= 1)
            mxs = fmaxf(mxs, __shfl_xor_sync(0xFFFFFFFFu, mxs, off));

        // pass A: exact fp32 logit per kept candidate (warp-cooperative dot)
        const float* mkb = mkey + (size_t)b * DK * NM;
        for (int i = 0; i < c; i++) {
            int2 e = (i < FCAND) ? sCand[wid][i] : g_cand[cbase + i];
            float snew = -3.0e38f;
            if (__int_as_float(e.y) > mxs - DELTAS) {
                int mg = g_mlist[b * NM + e.x];
                const float* mcol = mkb + mg;
                float part = 0.f;
#pragma unroll
                for (int r = 0; r < DK / 32; r++) {
                    int d = lane + r * 32;
                    part = fmaf(sQc[wid * DK + d], mcol[(size_t)d * NM], part);
                }
#pragma unroll
                for (int off = 16; off; off >>= 1)
                    part += __shfl_xor_sync(0xFFFFFFFFu, part, off);
                snew = part * PSCALAR;
                mx = fmaxf(mx, snew);
            }
            if (lane == 0) {
                if (i < FCAND) sCand[wid][i].y = __float_as_int(snew);
                else g_cand[cbase + i].y = __float_as_int(snew);
            }
        }
        __syncwarp();

        // pass B: deterministic fixed-point exp sum (exact logits)
        unsigned long long iacc = 0;
        for (int i = lane; i < c; i += 32) {
            float s = __int_as_float((i < FCAND) ? sCand[wid][i].y : g_cand[cbase + i].y);
            if (s > -1.0e37f) {
                float w = expf(s - mx);
                iacc += (unsigned long long)((double)w * 4503599627370496.0);  // 2^52
            }
        }
#pragma unroll
        for (int off = 16; off; off >>= 1)
            iacc += __shfl_xor_sync(0xFFFFFFFFu, iacc, off);
        double dsum = (double)iacc * (1.0 / 4503599627370496.0);
        inv = (float)(1.0 / dsum);

        // pass C: ascending-m extraction + mval column gather
        float ov[16];
#pragma unroll
        for (int j = 0; j < 16; j++) ov[j] = 0.f;

        const float* mvb = mval + (size_t)b * DV * NM;
        int last = -1;
        while (true) {
            int mym = 0x7FFFFFFF; float myw = 0.f;
            for (int i = lane; i < c; i += 32) {
                int2 e = (i < FCAND) ? sCand[wid][i] : g_cand[cbase + i];
                float s = __int_as_float(e.y);
                if (s > -1.0e37f && e.x > last && e.x < mym) {
                    mym = e.x;
                    myw = expf(s - mx);
                }
            }
#pragma unroll
            for (int off = 16; off; off >>= 1) {
                int om = __shfl_xor_sync(0xFFFFFFFFu, mym, off);
                float ow = __shfl_xor_sync(0xFFFFFFFFu, myw, off);
                if (om < mym) { mym = om; myw = ow; }
            }
            if (mym == 0x7FFFFFFF) break;
            int mg = g_mlist[b * NM + mym];
            const float* col = mvb + mg;
#pragma unroll
            for (int j = 0; j < 16; j++)
                ov[j] += myw * col[(size_t)(lane + 32 * j) * NM];
            last = mym;
        }

#pragma unroll
        for (int j = 0; j < 16; j++)
            sO[wid][lane + 32 * j] = ov[j] * inv;
    }
    __syncthreads();

    // grouped write: consecutive threads cover the 8 q's of one v
    float* ob = out + (size_t)b * DV * NQ;
    for (int idx = tid; idx < 8 * DV; idx += NTHREADS) {
        int v = idx >> 3, k = idx & 7;
        int qgk = sQg[k];
        if (qgk >= 0) ob[(size_t)v * NQ + qgk] = sO[k][v];
    }
}

// -------- launch --------
extern "C" void kernel_launch(void* const* d_in, const int* in_sizes, int n_in,
                              void* d_out, int out_size) {
    const float*        qkey  = (const float*)d_in[0];
    // d_in[1] = qval (unused by the reference math)
    const unsigned int* qmask = (const unsigned int*)d_in[2];
    const float*        mkey  = (const float*)d_in[3];
    const float*        mval  = (const float*)d_in[4];
    const unsigned int* mmask = (const unsigned int*)d_in[5];
    float* out = (float*)d_out;

    int n4 = BATCH * DV * NQ / 4;
    zero_kernel<<<(n4 + 255) / 256, 256>>>((float4*)out, n4);

    compact_kernel<<<dim3(BATCH, 2), NTHREADS>>>(qmask, mmask);

    pack_kernel<<<dim3((NQ + NM) / 32, 2, BATCH), dim3(32, 8)>>>(qkey, mkey);

    // launch #4 — ncu capture slot
    cudaFuncSetAttribute(qk_mma_kernel, cudaFuncAttributeMaxDynamicSharedMemorySize, SMQ_TOTAL);
    qk_mma_kernel<<<GRIDX, NTHREADS, SMQ_TOTAL>>>();

    finalize_kernel<<<dim3(NQ / 8, BATCH), NTHREADS>>>(qkey, mkey, mval, out);
}